// round 13
// baseline (speedup 1.0000x reference)
#include <cuda_runtime.h>
#include <math.h>

#define PTS    4096
#define BATCH  32
#define NBX    32
#define NBY    32
#define NCF    (NBX * NBY)              // 1024 fine cells (~4 pts/cell)
#define TPB    512
#define TPB_B  1024
#define TILES_PER_BLOCK 2
#define QTILES (PTS / TPB)              // 8 tiles of 512 queries
#define QBLOCKS (QTILES / TILES_PER_BLOCK) // 4 blocks per (batch,dir)
#define SMEM_SCAN (PTS * 16)            // 64KB dynamic: staged targets

// Fine-serpentine-ordered points, two views:
//   g_fine : PAIR-PACKED  {-2x0,-2x1,-2y0,-2y1}{-2z0,-2z1,g2_0,g2_1}  (targets)
//   g_plain: plain float4 {-2x,-2y,-2z,|p|^2}                         (queries)
__device__ float4 g_fine [2 * BATCH * PTS];
__device__ float4 g_plain[2 * BATCH * PTS];
__device__ int    g_cdfF [2 * BATCH * (NCF + 1)];
__device__ float4 g_meta [2 * BATCH];    // {x0, invwx, y0, invwy}

// Serpentine cell id: y runs upward in even columns, downward in odd ones.
__device__ __forceinline__ int serp_cell(int cx, int cy) {
    int cys = (cx & 1) ? (NBY - 1 - cy) : cy;
    return cx * NBY + cys;
}

// ---- Blackwell packed f32x2 helpers ----------------------------------------
__device__ __forceinline__ unsigned long long splat2(float v) {
    unsigned long long r;
    asm("mov.b64 %0, {%1, %1};" : "=l"(r) : "f"(v));
    return r;
}
__device__ __forceinline__ unsigned long long fma2(unsigned long long a,
                                                   unsigned long long b,
                                                   unsigned long long c) {
    unsigned long long d;
    asm("fma.rn.f32x2 %0, %1, %2, %3;" : "=l"(d) : "l"(a), "l"(b), "l"(c));
    return d;
}
__device__ __forceinline__ void min2_acc(unsigned long long t, float& a0, float& a1) {
    float lo, hi;
    asm("mov.b64 {%0, %1}, %2;" : "=f"(lo), "=f"(hi) : "l"(t));
    a0 = fminf(a0, lo);
    a1 = fminf(a1, hi);
}

// ---------------------------------------------------------------------------
// Kernel 1: per (batch,set) serpentine 2-D counting sort. Grid (BATCH, 2).
// ---------------------------------------------------------------------------
__global__ __launch_bounds__(TPB_B) void build_kernel(
    const float* __restrict__ pred, const float* __restrict__ gt,
    float* __restrict__ out)
{
    __shared__ unsigned hist[NCF];
    __shared__ unsigned offs[NCF];
    __shared__ unsigned wscan[32];
    __shared__ float    red[128];
    __shared__ float    sm[4];

    const int b = blockIdx.x, set = blockIdx.y, tid = threadIdx.x;
    const int lane = tid & 31, wid = tid >> 5;
    const unsigned FULL = 0xFFFFFFFFu;

    if (b == 0 && set == 0 && tid == 0) out[0] = 0.0f;

    const float* __restrict__ src = (set ? gt : pred) + (size_t)b * PTS * 3;

    // ---- pass 1: bbox of (x, y) ----
    float mnx = 3e38f, mxx = -3e38f, mny = 3e38f, mxy = -3e38f;
    for (int i = tid; i < PTS; i += TPB_B) {
        float x = src[3 * i], y = src[3 * i + 1];
        mnx = fminf(mnx, x); mxx = fmaxf(mxx, x);
        mny = fminf(mny, y); mxy = fmaxf(mxy, y);
    }
    #pragma unroll
    for (int o = 16; o > 0; o >>= 1) {
        mnx = fminf(mnx, __shfl_xor_sync(FULL, mnx, o));
        mxx = fmaxf(mxx, __shfl_xor_sync(FULL, mxx, o));
        mny = fminf(mny, __shfl_xor_sync(FULL, mny, o));
        mxy = fmaxf(mxy, __shfl_xor_sync(FULL, mxy, o));
    }
    if (lane == 0) { red[wid] = mnx; red[32 + wid] = mxx; red[64 + wid] = mny; red[96 + wid] = mxy; }
    if (tid < NCF) hist[tid] = 0;
    __syncthreads();
    if (tid == 0) {
        float a = red[0], c = red[32], e = red[64], f = red[96];
        #pragma unroll
        for (int i = 1; i < 32; i++) {
            a = fminf(a, red[i]);      c = fmaxf(c, red[32 + i]);
            e = fminf(e, red[64 + i]); f = fmaxf(f, red[96 + i]);
        }
        sm[0] = a; sm[1] = (float)NBX / fmaxf(c - a, 1e-30f);
        sm[2] = e; sm[3] = (float)NBY / fmaxf(f - e, 1e-30f);
        g_meta[set * BATCH + b] = make_float4(sm[0], sm[1], sm[2], sm[3]);
    }
    __syncthreads();
    const float x0 = sm[0], invwx = sm[1], y0 = sm[2], invwy = sm[3];

    // ---- pass 2: histogram (serpentine cells) ----
    for (int i = tid; i < PTS; i += TPB_B) {
        float x = src[3 * i], y = src[3 * i + 1];
        int cx = (int)fminf(fmaxf((x - x0) * invwx, 0.0f), (float)(NBX - 1));
        int cy = (int)fminf(fmaxf((y - y0) * invwy, 0.0f), (float)(NBY - 1));
        atomicAdd(&hist[serp_cell(cx, cy)], 1u);
    }
    __syncthreads();

    // ---- exclusive scan over 1024 ----
    unsigned v = (tid < NCF) ? hist[tid] : 0u;
    unsigned inc = v;
    #pragma unroll
    for (int o = 1; o < 32; o <<= 1) {
        unsigned n = __shfl_up_sync(FULL, inc, o);
        if (lane >= o) inc += n;
    }
    if (lane == 31) wscan[wid] = inc;
    __syncthreads();
    if (wid == 0) {
        unsigned wv = wscan[lane];
        #pragma unroll
        for (int o = 1; o < 32; o <<= 1) {
            unsigned n = __shfl_up_sync(FULL, wv, o);
            if (lane >= o) wv += n;
        }
        wscan[lane] = wv;
    }
    __syncthreads();
    const int base = (set * BATCH + b) * (NCF + 1);
    if (tid < NCF) {
        unsigned excl = inc - v + (wid ? wscan[wid - 1] : 0u);
        offs[tid] = excl;
        g_cdfF[base + tid] = (int)excl;
        if (tid == 0) g_cdfF[base + NCF] = PTS;
    }
    __syncthreads();

    // ---- pass 3: scatter to pair-packed (targets) and plain (queries) ----
    float*  __restrict__ dstF = (float*)(g_fine + (size_t)(set * BATCH + b) * PTS);
    float4* __restrict__ dstP = g_plain + (size_t)(set * BATCH + b) * PTS;
    for (int i = tid; i < PTS; i += TPB_B) {
        float x = src[3 * i], y = src[3 * i + 1], z = src[3 * i + 2];
        int cx = (int)fminf(fmaxf((x - x0) * invwx, 0.0f), (float)(NBX - 1));
        int cy = (int)fminf(fmaxf((y - y0) * invwy, 0.0f), (float)(NBY - 1));
        float g2 = fmaf(x, x, fmaf(y, y, z * z));
        unsigned p = atomicAdd(&offs[serp_cell(cx, cy)], 1u);
        float* df = dstF + (size_t)(p >> 1) * 8 + (p & 1);
        df[0] = -2.0f * x; df[2] = -2.0f * y; df[4] = -2.0f * z; df[6] = g2;
        dstP[p] = make_float4(-2.0f * x, -2.0f * y, -2.0f * z, g2);
    }
}

// ---------------------------------------------------------------------------
// Kernel 2: ring-expansion NN scan, 2 query tiles per block (single wave).
// Grid (QBLOCKS, BATCH, 2), 512 threads, >=3 blocks/SM.
// ---------------------------------------------------------------------------
__global__ __launch_bounds__(TPB, 3) void chamfer_scan_kernel(float* __restrict__ out)
{
    extern __shared__ float4 st[];          // 4096 float4 = 2048 packed pairs
    __shared__ int scdf[NCF + 1];

    const int qb = blockIdx.x, b = blockIdx.y, dir = blockIdx.z;
    const int tid = threadIdx.x;
    const unsigned FULL = 0xFFFFFFFFu;
    const int lane = tid & 31;

    const int qset = dir ? 0 : 1;
    const int tset = dir ? 1 : 0;
    const float4* __restrict__ qry = g_plain + (size_t)(qset * BATCH + b) * PTS;
    const float4* __restrict__ tgt = g_fine  + (size_t)(tset * BATCH + b) * PTS;
    const int*    __restrict__ cdf = g_cdfF + (tset * BATCH + b) * (NCF + 1);

    for (int i = tid; i < PTS; i += TPB) st[i] = __ldg(&tgt[i]);
    for (int i = tid; i < NCF + 1; i += TPB) scdf[i] = __ldg(&cdf[i]);
    __syncthreads();

    const float4 m = __ldg(&g_meta[tset * BATCH + b]);
    const float x0 = m.x, invwx = m.y, y0 = m.z, invwy = m.w;
    const float wx = 1.0f / invwx, wy = 1.0f / invwy;
    const ulonglong2* __restrict__ sp = (const ulonglong2*)st;

    float tsum = 0.0f;

    #pragma unroll
    for (int t = 0; t < TILES_PER_BLOCK; ++t) {
        const int qt = qb * TILES_PER_BLOCK + t;
        const float4 qp = __ldg(&qry[qt * TPB + tid]);
        const float px = -0.5f * qp.x, py = -0.5f * qp.y;
        const float p2 = qp.w;
        const unsigned long long sqx = splat2(qp.x * -0.5f),
                                 sqy = splat2(qp.y * -0.5f),
                                 sqz = splat2(qp.z * -0.5f);

        // Warp bbox of queries (tight thanks to serpentine ordering).
        float qxl = px, qxh = px, qyl = py, qyh = py;
        #pragma unroll
        for (int o = 16; o > 0; o >>= 1) {
            qxl = fminf(qxl, __shfl_xor_sync(FULL, qxl, o));
            qxh = fmaxf(qxh, __shfl_xor_sync(FULL, qxh, o));
            qyl = fminf(qyl, __shfl_xor_sync(FULL, qyl, o));
            qyh = fmaxf(qyh, __shfl_xor_sync(FULL, qyh, o));
        }

        float bt0 = 3e38f, bt1 = 3e38f, bt2 = 3e38f, bt3 = 3e38f;

        #define PAIR(JP, A0, A1) {                                             \
            ulonglong2 u0 = sp[2 * (JP)];                                      \
            ulonglong2 u1 = sp[2 * (JP) + 1];                                  \
            unsigned long long tt =                                            \
                fma2(sqz, u1.x, fma2(sqy, u0.y, fma2(sqx, u0.x, u1.y)));       \
            min2_acc(tt, A0, A1);                                              \
        }
        #define SCAN_RANGE(LO, HI) {                                           \
            int jp = (LO) >> 1, je = ((HI) + 1) >> 1;                          \
            for (; jp + 2 <= je; jp += 2) { PAIR(jp, bt0, bt1) PAIR(jp + 1, bt2, bt3) } \
            for (; jp < je; ++jp) PAIR(jp, bt0, bt1)                           \
        }
        #define SCAN_COL(BX, YA, YB) {                                         \
            int ya_ = (YA), yb_ = (YB);                                        \
            int a_  = ((BX) & 1) ? (NBY - 1 - yb_) : ya_;                      \
            int b2_ = ((BX) & 1) ? (NBY - 1 - ya_) : yb_;                      \
            int s_ = scdf[(BX) * NBY + a_];                                    \
            int e_ = scdf[(BX) * NBY + b2_ + 1];                               \
            SCAN_RANGE(s_, e_)                                                 \
        }

        // ---- Ring 0: warp bbox +- 1 cell ----
        int cXl = max((int)fminf(fmaxf((qxl - x0) * invwx, 0.0f), (float)(NBX - 1)) - 1, 0);
        int cXh = min((int)fminf(fmaxf((qxh - x0) * invwx, 0.0f), (float)(NBX - 1)) + 1, NBX - 1);
        int cYl = max((int)fminf(fmaxf((qyl - y0) * invwy, 0.0f), (float)(NBY - 1)) - 1, 0);
        int cYh = min((int)fminf(fmaxf((qyh - y0) * invwy, 0.0f), (float)(NBY - 1)) + 1, NBY - 1);
        for (int bx = cXl; bx <= cXh; ++bx) SCAN_COL(bx, cYl, cYh)

        // ---- Ring expansion (squared certification: no sqrt in loop) ----
        for (;;) {
            float bt = fminf(fminf(bt0, bt1), fminf(bt2, bt3));
            float d2best = fmaxf(bt + p2, 0.0f) * 1.00001f + 1e-5f;
            float db = 3e38f;
            if (cXl > 0)       db = fminf(db, px - (x0 + (float)cXl * wx));
            if (cXh < NBX - 1) db = fminf(db, (x0 + (float)(cXh + 1) * wx) - px);
            if (cYl > 0)       db = fminf(db, py - (y0 + (float)cYl * wy));
            if (cYh < NBY - 1) db = fminf(db, (y0 + (float)(cYh + 1) * wy) - py);
            if (__all_sync(FULL, d2best <= db * db)) break;

            int nXl = max(cXl - 1, 0), nXh = min(cXh + 1, NBX - 1);
            int nYl = max(cYl - 1, 0), nYh = min(cYh + 1, NBY - 1);
            if (nXl < cXl) SCAN_COL(nXl, nYl, nYh)
            if (nXh > cXh) SCAN_COL(nXh, nYl, nYh)
            for (int bx = cXl; bx <= cXh; ++bx) {
                if (nYl < cYl) SCAN_COL(bx, nYl, cYl - 1)
                if (nYh > cYh) SCAN_COL(bx, cYh + 1, nYh)
            }
            cXl = nXl; cXh = nXh; cYl = nYl; cYh = nYh;
        }
        #undef SCAN_COL
        #undef SCAN_RANGE
        #undef PAIR

        float bt = fminf(fminf(bt0, bt1), fminf(bt2, bt3));
        tsum += sqrtf(fmaxf(bt + p2, 1e-12f));
    }

    // ---- Block sum reduction + single atomic into out ----
    #pragma unroll
    for (int o = 16; o > 0; o >>= 1)
        tsum += __shfl_down_sync(FULL, tsum, o);

    __shared__ float wsum[TPB / 32];
    const int wid = tid >> 5;
    if (lane == 0) wsum[wid] = tsum;
    __syncthreads();
    if (tid < TPB / 32) {
        float v = wsum[tid];
        #pragma unroll
        for (int o = (TPB / 32) / 2; o > 0; o >>= 1)
            v += __shfl_down_sync(FULL, v, o, TPB / 32);
        if (tid == 0)
            atomicAdd(out, v * (1.0f / (float)(BATCH * PTS)));
    }
}

extern "C" void kernel_launch(void* const* d_in, const int* in_sizes, int n_in,
                              void* d_out, int out_size)
{
    (void)in_sizes; (void)n_in; (void)out_size;
    const float* pred = (const float*)d_in[0];
    const float* gt   = (const float*)d_in[1];
    float* out        = (float*)d_out;

    cudaFuncSetAttribute(chamfer_scan_kernel,
                         cudaFuncAttributeMaxDynamicSharedMemorySize, SMEM_SCAN);

    dim3 bgrid(BATCH, 2);
    build_kernel<<<bgrid, TPB_B>>>(pred, gt, out);

    dim3 sgrid(QBLOCKS, BATCH, 2);
    chamfer_scan_kernel<<<sgrid, TPB, SMEM_SCAN>>>(out);
}

// round 15
// speedup vs baseline: 1.3230x; 1.3230x over previous
#include <cuda_runtime.h>
#include <math.h>

#define PTS    4096
#define BATCH  32
#define NBX    32
#define NBY    32
#define NCF    (NBX * NBY)              // 1024 fine cells (~4 pts/cell)
#define TPB    512
#define TPB_B  1024
#define QTILES (PTS / TPB)              // 8 tiles of 512 queries
#define NTICKETS (2 * BATCH * QTILES)   // 512
#define NBLOCKS  444                    // 3 blocks/SM x 148 SMs: one full wave
#define SMEM_SCAN (PTS * 16)            // 64KB dynamic: staged targets

// Fine-serpentine-ordered points, two views:
//   g_fine : PAIR-PACKED  {-2x0,-2x1,-2y0,-2y1}{-2z0,-2z1,g2_0,g2_1}  (targets)
//   g_plain: plain float4 {-2x,-2y,-2z,|p|^2}                         (queries)
__device__ float4 g_fine [2 * BATCH * PTS];
__device__ float4 g_plain[2 * BATCH * PTS];
__device__ int    g_cdfF [2 * BATCH * (NCF + 1)];
__device__ float4 g_meta [2 * BATCH];    // {x0, invwx, y0, invwy}
__device__ int    g_ticket;

// Serpentine cell id: y runs upward in even columns, downward in odd ones.
__device__ __forceinline__ int serp_cell(int cx, int cy) {
    int cys = (cx & 1) ? (NBY - 1 - cy) : cy;
    return cx * NBY + cys;
}

// ---- Blackwell packed f32x2 helpers ----------------------------------------
__device__ __forceinline__ unsigned long long splat2(float v) {
    unsigned long long r;
    asm("mov.b64 %0, {%1, %1};" : "=l"(r) : "f"(v));
    return r;
}
__device__ __forceinline__ unsigned long long fma2(unsigned long long a,
                                                   unsigned long long b,
                                                   unsigned long long c) {
    unsigned long long d;
    asm("fma.rn.f32x2 %0, %1, %2, %3;" : "=l"(d) : "l"(a), "l"(b), "l"(c));
    return d;
}
__device__ __forceinline__ void min2_acc(unsigned long long t, float& a0, float& a1) {
    float lo, hi;
    asm("mov.b64 {%0, %1}, %2;" : "=f"(lo), "=f"(hi) : "l"(t));
    a0 = fminf(a0, lo);
    a1 = fminf(a1, hi);
}

// ---------------------------------------------------------------------------
// Kernel 1: per (batch,set) serpentine 2-D counting sort. Grid (BATCH, 2).
// Also resets the ticket counter and output scalar.
// ---------------------------------------------------------------------------
__global__ __launch_bounds__(TPB_B) void build_kernel(
    const float* __restrict__ pred, const float* __restrict__ gt,
    float* __restrict__ out)
{
    __shared__ unsigned hist[NCF];
    __shared__ unsigned offs[NCF];
    __shared__ unsigned wscan[32];
    __shared__ float    red[128];
    __shared__ float    sm[4];

    const int b = blockIdx.x, set = blockIdx.y, tid = threadIdx.x;
    const int lane = tid & 31, wid = tid >> 5;
    const unsigned FULL = 0xFFFFFFFFu;

    if (b == 0 && set == 0 && tid == 0) { out[0] = 0.0f; g_ticket = 0; }

    const float* __restrict__ src = (set ? gt : pred) + (size_t)b * PTS * 3;

    // ---- pass 1: bbox of (x, y) ----
    float mnx = 3e38f, mxx = -3e38f, mny = 3e38f, mxy = -3e38f;
    for (int i = tid; i < PTS; i += TPB_B) {
        float x = src[3 * i], y = src[3 * i + 1];
        mnx = fminf(mnx, x); mxx = fmaxf(mxx, x);
        mny = fminf(mny, y); mxy = fmaxf(mxy, y);
    }
    #pragma unroll
    for (int o = 16; o > 0; o >>= 1) {
        mnx = fminf(mnx, __shfl_xor_sync(FULL, mnx, o));
        mxx = fmaxf(mxx, __shfl_xor_sync(FULL, mxx, o));
        mny = fminf(mny, __shfl_xor_sync(FULL, mny, o));
        mxy = fmaxf(mxy, __shfl_xor_sync(FULL, mxy, o));
    }
    if (lane == 0) { red[wid] = mnx; red[32 + wid] = mxx; red[64 + wid] = mny; red[96 + wid] = mxy; }
    if (tid < NCF) hist[tid] = 0;
    __syncthreads();
    if (tid == 0) {
        float a = red[0], c = red[32], e = red[64], f = red[96];
        #pragma unroll
        for (int i = 1; i < 32; i++) {
            a = fminf(a, red[i]);      c = fmaxf(c, red[32 + i]);
            e = fminf(e, red[64 + i]); f = fmaxf(f, red[96 + i]);
        }
        sm[0] = a; sm[1] = (float)NBX / fmaxf(c - a, 1e-30f);
        sm[2] = e; sm[3] = (float)NBY / fmaxf(f - e, 1e-30f);
        g_meta[set * BATCH + b] = make_float4(sm[0], sm[1], sm[2], sm[3]);
    }
    __syncthreads();
    const float x0 = sm[0], invwx = sm[1], y0 = sm[2], invwy = sm[3];

    // ---- pass 2: histogram (serpentine cells) ----
    for (int i = tid; i < PTS; i += TPB_B) {
        float x = src[3 * i], y = src[3 * i + 1];
        int cx = (int)fminf(fmaxf((x - x0) * invwx, 0.0f), (float)(NBX - 1));
        int cy = (int)fminf(fmaxf((y - y0) * invwy, 0.0f), (float)(NBY - 1));
        atomicAdd(&hist[serp_cell(cx, cy)], 1u);
    }
    __syncthreads();

    // ---- exclusive scan over 1024 ----
    unsigned v = (tid < NCF) ? hist[tid] : 0u;
    unsigned inc = v;
    #pragma unroll
    for (int o = 1; o < 32; o <<= 1) {
        unsigned n = __shfl_up_sync(FULL, inc, o);
        if (lane >= o) inc += n;
    }
    if (lane == 31) wscan[wid] = inc;
    __syncthreads();
    if (wid == 0) {
        unsigned wv = wscan[lane];
        #pragma unroll
        for (int o = 1; o < 32; o <<= 1) {
            unsigned n = __shfl_up_sync(FULL, wv, o);
            if (lane >= o) wv += n;
        }
        wscan[lane] = wv;
    }
    __syncthreads();
    const int base = (set * BATCH + b) * (NCF + 1);
    if (tid < NCF) {
        unsigned excl = inc - v + (wid ? wscan[wid - 1] : 0u);
        offs[tid] = excl;
        g_cdfF[base + tid] = (int)excl;
        if (tid == 0) g_cdfF[base + NCF] = PTS;
    }
    __syncthreads();

    // ---- pass 3: scatter to pair-packed (targets) and plain (queries) ----
    float*  __restrict__ dstF = (float*)(g_fine + (size_t)(set * BATCH + b) * PTS);
    float4* __restrict__ dstP = g_plain + (size_t)(set * BATCH + b) * PTS;
    for (int i = tid; i < PTS; i += TPB_B) {
        float x = src[3 * i], y = src[3 * i + 1], z = src[3 * i + 2];
        int cx = (int)fminf(fmaxf((x - x0) * invwx, 0.0f), (float)(NBX - 1));
        int cy = (int)fminf(fmaxf((y - y0) * invwy, 0.0f), (float)(NBY - 1));
        float g2 = fmaf(x, x, fmaf(y, y, z * z));
        unsigned p = atomicAdd(&offs[serp_cell(cx, cy)], 1u);
        float* df = dstF + (size_t)(p >> 1) * 8 + (p & 1);
        df[0] = -2.0f * x; df[2] = -2.0f * y; df[4] = -2.0f * z; df[6] = g2;
        dstP[p] = make_float4(-2.0f * x, -2.0f * y, -2.0f * z, g2);
    }
}

// ---------------------------------------------------------------------------
// Kernel 2: persistent ring-expansion NN scan with ticket work-stealing.
// Grid 444 x 512 threads (one full wave at 3 blocks/SM). Tickets are
// (b,dir)-major so consecutive tickets usually reuse the staged target set.
// Every loop iteration is bracketed by __syncthreads() (fetch + end of body),
// so restage writes are strictly ordered against all prior reads.
// ---------------------------------------------------------------------------
__global__ __launch_bounds__(TPB, 3) void chamfer_scan_kernel(float* __restrict__ out)
{
    extern __shared__ float4 st[];          // 4096 float4 = 2048 packed pairs
    __shared__ int   scdf[NCF + 1];
    __shared__ int   s_ticket;
    __shared__ float wsum[TPB / 32];

    const int tid = threadIdx.x;
    const unsigned FULL = 0xFFFFFFFFu;
    const int lane = tid & 31;

    float tsum = 0.0f;
    int cur_key = -1;
    float x0 = 0.f, invwx = 1.f, y0 = 0.f, invwy = 1.f, wx = 1.f, wy = 1.f;
    const float4* qry = g_plain;

    for (;;) {
        if (tid == 0) s_ticket = atomicAdd(&g_ticket, 1);
        __syncthreads();
        const int t = s_ticket;
        if (t >= NTICKETS) break;

        // Decode: (b, dir) major, qt minor.
        const int key = t >> 3;              // b*2 + dir
        const int qt  = t & 7;
        const int b   = key >> 1;
        const int dir = key & 1;
        const int qset = dir ? 0 : 1;
        const int tset = dir ? 1 : 0;

        if (key != cur_key) {
            const float4* tgt = g_fine + (size_t)(tset * BATCH + b) * PTS;
            const int*    cdf = g_cdfF + (tset * BATCH + b) * (NCF + 1);
            for (int i = tid; i < PTS; i += TPB) st[i] = __ldg(&tgt[i]);
            for (int i = tid; i < NCF + 1; i += TPB) scdf[i] = __ldg(&cdf[i]);
            __syncthreads();
            const float4 m = __ldg(&g_meta[tset * BATCH + b]);
            x0 = m.x; invwx = m.y; y0 = m.z; invwy = m.w;
            wx = 1.0f / invwx; wy = 1.0f / invwy;
            qry = g_plain + (size_t)(qset * BATCH + b) * PTS;
            cur_key = key;
        }

        const ulonglong2* sp = (const ulonglong2*)st;
        const float4 qp = __ldg(&qry[qt * TPB + tid]);
        const float px = -0.5f * qp.x, py = -0.5f * qp.y;
        const float p2 = qp.w;
        const unsigned long long sqx = splat2(qp.x * -0.5f),
                                 sqy = splat2(qp.y * -0.5f),
                                 sqz = splat2(qp.z * -0.5f);

        // Warp bbox of queries (tight thanks to serpentine ordering).
        float qxl = px, qxh = px, qyl = py, qyh = py;
        #pragma unroll
        for (int o = 16; o > 0; o >>= 1) {
            qxl = fminf(qxl, __shfl_xor_sync(FULL, qxl, o));
            qxh = fmaxf(qxh, __shfl_xor_sync(FULL, qxh, o));
            qyl = fminf(qyl, __shfl_xor_sync(FULL, qyl, o));
            qyh = fmaxf(qyh, __shfl_xor_sync(FULL, qyh, o));
        }

        float bt0 = 3e38f, bt1 = 3e38f, bt2 = 3e38f, bt3 = 3e38f;

        #define PAIR(JP, A0, A1) {                                             \
            ulonglong2 u0 = sp[2 * (JP)];                                      \
            ulonglong2 u1 = sp[2 * (JP) + 1];                                  \
            unsigned long long tt =                                            \
                fma2(sqz, u1.x, fma2(sqy, u0.y, fma2(sqx, u0.x, u1.y)));       \
            min2_acc(tt, A0, A1);                                              \
        }
        #define SCAN_RANGE(LO, HI) {                                           \
            int jp = (LO) >> 1, je = ((HI) + 1) >> 1;                          \
            for (; jp + 2 <= je; jp += 2) { PAIR(jp, bt0, bt1) PAIR(jp + 1, bt2, bt3) } \
            for (; jp < je; ++jp) PAIR(jp, bt0, bt1)                           \
        }
        #define SCAN_COL(BX, YA, YB) {                                         \
            int ya_ = (YA), yb_ = (YB);                                        \
            int a_  = ((BX) & 1) ? (NBY - 1 - yb_) : ya_;                      \
            int b2_ = ((BX) & 1) ? (NBY - 1 - ya_) : yb_;                      \
            int s_ = scdf[(BX) * NBY + a_];                                    \
            int e_ = scdf[(BX) * NBY + b2_ + 1];                               \
            SCAN_RANGE(s_, e_)                                                 \
        }

        // ---- Ring 0: warp bbox +- 1 cell ----
        int cXl = max((int)fminf(fmaxf((qxl - x0) * invwx, 0.0f), (float)(NBX - 1)) - 1, 0);
        int cXh = min((int)fminf(fmaxf((qxh - x0) * invwx, 0.0f), (float)(NBX - 1)) + 1, NBX - 1);
        int cYl = max((int)fminf(fmaxf((qyl - y0) * invwy, 0.0f), (float)(NBY - 1)) - 1, 0);
        int cYh = min((int)fminf(fmaxf((qyh - y0) * invwy, 0.0f), (float)(NBY - 1)) + 1, NBY - 1);
        for (int bx = cXl; bx <= cXh; ++bx) SCAN_COL(bx, cYl, cYh)

        // ---- Ring expansion (squared certification: no sqrt in loop) ----
        for (;;) {
            float bt = fminf(fminf(bt0, bt1), fminf(bt2, bt3));
            float d2best = fmaxf(bt + p2, 0.0f) * 1.00001f + 1e-5f;
            float db = 3e38f;
            if (cXl > 0)       db = fminf(db, px - (x0 + (float)cXl * wx));
            if (cXh < NBX - 1) db = fminf(db, (x0 + (float)(cXh + 1) * wx) - px);
            if (cYl > 0)       db = fminf(db, py - (y0 + (float)cYl * wy));
            if (cYh < NBY - 1) db = fminf(db, (y0 + (float)(cYh + 1) * wy) - py);
            if (__all_sync(FULL, d2best <= db * db)) break;

            int nXl = max(cXl - 1, 0), nXh = min(cXh + 1, NBX - 1);
            int nYl = max(cYl - 1, 0), nYh = min(cYh + 1, NBY - 1);
            if (nXl < cXl) SCAN_COL(nXl, nYl, nYh)
            if (nXh > cXh) SCAN_COL(nXh, nYl, nYh)
            for (int bx = cXl; bx <= cXh; ++bx) {
                if (nYl < cYl) SCAN_COL(bx, nYl, cYl - 1)
                if (nYh > cYh) SCAN_COL(bx, cYh + 1, nYh)
            }
            cXl = nXl; cXh = nXh; cYl = nYl; cYh = nYh;
        }
        #undef SCAN_COL
        #undef SCAN_RANGE
        #undef PAIR

        float bt = fminf(fminf(bt0, bt1), fminf(bt2, bt3));
        tsum += sqrtf(fmaxf(bt + p2, 1e-12f));

        // End-of-body barrier: orders this ticket's reads before any restage
        // writes of the next ticket, unconditionally.
        __syncthreads();
    }

    // ---- Block sum reduction + single atomic into out ----
    #pragma unroll
    for (int o = 16; o > 0; o >>= 1)
        tsum += __shfl_down_sync(FULL, tsum, o);

    const int wid = tid >> 5;
    if (lane == 0) wsum[wid] = tsum;
    __syncthreads();
    if (wid == 0) {                       // whole warp 0 participates: no UB
        float v = (lane < TPB / 32) ? wsum[lane] : 0.0f;
        #pragma unroll
        for (int o = 16; o > 0; o >>= 1)
            v += __shfl_down_sync(FULL, v, o);
        if (lane == 0)
            atomicAdd(out, v * (1.0f / (float)(BATCH * PTS)));
    }
}

extern "C" void kernel_launch(void* const* d_in, const int* in_sizes, int n_in,
                              void* d_out, int out_size)
{
    (void)in_sizes; (void)n_in; (void)out_size;
    const float* pred = (const float*)d_in[0];
    const float* gt   = (const float*)d_in[1];
    float* out        = (float*)d_out;

    cudaFuncSetAttribute(chamfer_scan_kernel,
                         cudaFuncAttributeMaxDynamicSharedMemorySize, SMEM_SCAN);

    dim3 bgrid(BATCH, 2);
    build_kernel<<<bgrid, TPB_B>>>(pred, gt, out);

    chamfer_scan_kernel<<<NBLOCKS, TPB, SMEM_SCAN>>>(out);
}